// round 10
// baseline (speedup 1.0000x reference)
#include <cuda_runtime.h>
#include <cuda_fp16.h>
#include <cstdint>

#define NCLS   13
#define PD     128
#define BM     64
#define NTHR   256
#define MINPTS 256.0f

// packed fp16 weight offsets (K padded to mult of 16), element counts in halfs
#define OFF1 0                    // 16*256   = 4096
#define OFF2 4096                 // 256*512  = 131072
#define OFF3 (OFF2 + 131072)      // 512*256  = 131072
#define OFF4 (OFF3 + 131072)      // 256*128  = 32768
#define WPTOT (OFF4 + 32768)

__device__ __align__(16) __half g_wp[WPTOT];
__device__ float  g_sums[NCLS * PD];
__device__ int    g_counts[NCLS];

// ---- fp16 mma m16n8k16, f32 accumulate ----
__device__ __forceinline__ void mma_f16(float* c, uint32_t a0, uint32_t a1,
                                        uint32_t a2, uint32_t a3,
                                        uint32_t b0, uint32_t b1) {
    asm volatile(
        "mma.sync.aligned.m16n8k16.row.col.f32.f16.f16.f32 "
        "{%0,%1,%2,%3}, {%4,%5,%6,%7}, {%8,%9}, {%0,%1,%2,%3};\n"
        : "+f"(c[0]), "+f"(c[1]), "+f"(c[2]), "+f"(c[3])
        : "r"(a0), "r"(a1), "r"(a2), "r"(a3), "r"(b0), "r"(b1));
}
// ---- fp16 mma m16n8k16, f16 accumulate (2x rate) ----
__device__ __forceinline__ void mma_h16(uint32_t* c, uint32_t a0, uint32_t a1,
                                        uint32_t a2, uint32_t a3,
                                        uint32_t b0, uint32_t b1) {
    asm volatile(
        "mma.sync.aligned.m16n8k16.row.col.f16.f16.f16.f16 "
        "{%0,%1}, {%2,%3,%4,%5}, {%6,%7}, {%0,%1};\n"
        : "+r"(c[0]), "+r"(c[1])
        : "r"(a0), "r"(a1), "r"(a2), "r"(a3), "r"(b0), "r"(b1));
}

// slot32: permutation within a 32-col double k-group.
// c -> r*8 + g*4 + hi*2 + low  (r=(c&6)>>1, g=(c>>4)&1, hi=(c>>3)&1, low=c&1)
// => lane's fragments for BOTH k-groups are 8 contiguous halfs (one LDS.128).
__device__ __forceinline__ int slot32(int c) {
    return (c & ~31) | ((c & 6) << 2) | ((c & 16) >> 2) | ((c & 8) >> 2) | (c & 1);
}

// ---------------- kernel 0: zero scratch ----------------
__global__ void zero_kernel() {
    int i = blockIdx.x * blockDim.x + threadIdx.x;
    if (i < NCLS * PD) g_sums[i] = 0.f;
    if (i < NCLS) g_counts[i] = 0;
}

// ---------------- kernel 1: per-class counts ----------------
__global__ void count_kernel(const int* __restrict__ y, int P) {
    __shared__ int sc[NCLS];
    if (threadIdx.x < NCLS) sc[threadIdx.x] = 0;
    __syncthreads();
    for (int i = blockIdx.x * blockDim.x + threadIdx.x; i < P;
         i += gridDim.x * blockDim.x)
        atomicAdd(&sc[y[i]], 1);
    __syncthreads();
    if (threadIdx.x < NCLS) atomicAdd(&g_counts[threadIdx.x], sc[threadIdx.x]);
}

// ---------------- kernel 2: pack ALL weights (pair-packed for LDG.128) ----------------
// 8 halfs per (jp,kc,lane): [j=2jp frag (4h)][j=2jp+1 frag (4h)]
// frag halfs: [k0,k0+1,k0+8,k0+9], k0 = kc*16 + 2r, n = j*8 + q  (r=lane&3, q=lane>>2)
__device__ __forceinline__ void pack_one(const float* __restrict__ src,
                                         __half* __restrict__ dst,
                                         int p, int K, int N, int Ksrc) {
    int t = p & 3;
    int h = (p >> 2) & 1;
    int lane = (p >> 3) & 31;
    int rest = p >> 8;
    int kc = rest % (K >> 4);
    int jp = rest / (K >> 4);
    int r = lane & 3, q = lane >> 2;
    int j = jp * 2 + h;
    int k = kc * 16 + 2 * r + (t & 1) + 8 * (t >> 1);
    int n = j * 8 + q;
    float v = (k < Ksrc) ? src[k * N + n] : 0.f;
    dst[p] = __float2half(v);
}
__global__ void pack_all_kernel(const float* __restrict__ We1, const float* __restrict__ We2,
                                const float* __restrict__ W1, const float* __restrict__ W2) {
    int p = blockIdx.x * blockDim.x + threadIdx.x;
    if (p < 4096)                    pack_one(We1, g_wp + OFF1, p, 16, 256, 7);
    else if (p < 4096 + 131072)      pack_one(We2, g_wp + OFF2, p - 4096, 256, 512, 256);
    else if (p < 4096 + 262144)      pack_one(W1,  g_wp + OFF3, p - 135168, 512, 256, 512);
    else if (p < WPTOT)              pack_one(W2,  g_wp + OFF4, p - 266240, 256, 128, 256);
}

// ---------------- fp16 mma layer ----------------
// A in shared: row-major halfs [BM][ASTR], slot32-permuted double k-groups.
// ASTR mod 64 == 32 (stride bytes ≡ 64 mod 128) -> conflict-free LDS.128:
//   phase lanes (q in {0,1}, r in {0..3}) cover q*64 + r*16 = 0..127 exactly.
// One uint4 A load = fragments for kc=2*kc2 (.x,.y) and kc=2*kc2+1 (.z,.w).
// W pair-packed: one uint4 per (jp,kc,lane).
// HACC: f16 accumulation, 2 chains (even/odd k-group), f32 combine at epilogue.
template <int K, int N, int ASTR, int CSTR, int MT, int NT, bool LASTL, bool HACC>
__device__ __forceinline__ void mma_layer(
    const __half* __restrict__ Wp, const float* __restrict__ bias,
    const __half* __restrict__ Ash, void* __restrict__ Cout,
    int warp, int lane)
{
    const int r = lane & 3, q = lane >> 2;
    constexpr int SLICE = N / 8;
    constexpr int NCH = SLICE / (NT * 8);
    constexpr int KC = K / 16;
    constexpr int KC2 = (K + 31) / 32;
    constexpr bool HASODD = (K % 32) == 0;
    #pragma unroll
    for (int ch = 0; ch < NCH; ch++) {
        const int nbase = warp * SLICE + ch * NT * 8;
        const int jp0 = nbase >> 4;
        float acc[HACC ? 1 : MT][NT][HACC ? 1 : 4];
        uint32_t hacc[HACC ? MT : 1][NT][HACC ? 4 : 1];
        if (HACC) {
            #pragma unroll
            for (int mt = 0; mt < MT; mt++)
                #pragma unroll
                for (int nt = 0; nt < NT; nt++)
                    #pragma unroll
                    for (int i = 0; i < 4; i++) hacc[mt][nt][i] = 0u;
        } else {
            #pragma unroll
            for (int mt = 0; mt < MT; mt++)
                #pragma unroll
                for (int nt = 0; nt < NT; nt++)
                    #pragma unroll
                    for (int i = 0; i < 4; i++) acc[mt][nt][i] = 0.f;
        }

        #pragma unroll 2
        for (int kc2 = 0; kc2 < KC2; kc2++) {
            uint4 a[MT][2];
            #pragma unroll
            for (int mt = 0; mt < MT; mt++) {
                a[mt][0] = *(const uint4*)&Ash[(mt * 16 + q)     * ASTR + kc2 * 32 + r * 8];
                a[mt][1] = *(const uint4*)&Ash[(mt * 16 + q + 8) * ASTR + kc2 * 32 + r * 8];
            }
            // even k-group
            {
                const int kc = 2 * kc2;
                uint4 bp[NT / 2];
                #pragma unroll
                for (int n2 = 0; n2 < NT / 2; n2++)
                    bp[n2] = *(const uint4*)&Wp[(size_t)(((jp0 + n2) * KC + kc) * 32 + lane) * 8];
                #pragma unroll
                for (int mt = 0; mt < MT; mt++)
                    #pragma unroll
                    for (int n2 = 0; n2 < NT / 2; n2++) {
                        if (HACC) {
                            mma_h16(&hacc[mt][2*n2][0],   a[mt][0].x, a[mt][1].x,
                                    a[mt][0].y, a[mt][1].y, bp[n2].x, bp[n2].y);
                            mma_h16(&hacc[mt][2*n2+1][0], a[mt][0].x, a[mt][1].x,
                                    a[mt][0].y, a[mt][1].y, bp[n2].z, bp[n2].w);
                        } else {
                            mma_f16(acc[mt][2*n2],   a[mt][0].x, a[mt][1].x,
                                    a[mt][0].y, a[mt][1].y, bp[n2].x, bp[n2].y);
                            mma_f16(acc[mt][2*n2+1], a[mt][0].x, a[mt][1].x,
                                    a[mt][0].y, a[mt][1].y, bp[n2].z, bp[n2].w);
                        }
                    }
            }
            // odd k-group (absent when K == 16)
            if (HASODD) {
                const int kc = 2 * kc2 + 1;
                uint4 bp[NT / 2];
                #pragma unroll
                for (int n2 = 0; n2 < NT / 2; n2++)
                    bp[n2] = *(const uint4*)&Wp[(size_t)(((jp0 + n2) * KC + kc) * 32 + lane) * 8];
                #pragma unroll
                for (int mt = 0; mt < MT; mt++)
                    #pragma unroll
                    for (int n2 = 0; n2 < NT / 2; n2++) {
                        if (HACC) {
                            mma_h16(&hacc[mt][2*n2][2],   a[mt][0].z, a[mt][1].z,
                                    a[mt][0].w, a[mt][1].w, bp[n2].x, bp[n2].y);
                            mma_h16(&hacc[mt][2*n2+1][2], a[mt][0].z, a[mt][1].z,
                                    a[mt][0].w, a[mt][1].w, bp[n2].z, bp[n2].w);
                        } else {
                            mma_f16(acc[mt][2*n2],   a[mt][0].z, a[mt][1].z,
                                    a[mt][0].w, a[mt][1].w, bp[n2].x, bp[n2].y);
                            mma_f16(acc[mt][2*n2+1], a[mt][0].z, a[mt][1].z,
                                    a[mt][0].w, a[mt][1].w, bp[n2].z, bp[n2].w);
                        }
                    }
            }
        }
        // epilogue: bias + relu
        #pragma unroll
        for (int nt = 0; nt < NT; nt++) {
            int c0 = nbase + nt * 8 + 2 * r;
            float b0 = bias[c0], b1 = bias[c0 + 1];
            #pragma unroll
            for (int mt = 0; mt < MT; mt++) {
                int m0 = mt * 16 + q, m1 = m0 + 8;
                float v00, v01, v10, v11;
                if (HACC) {
                    __half2 h0 = __hadd2(*(__half2*)&hacc[mt][nt][0], *(__half2*)&hacc[mt][nt][2]);
                    __half2 h1 = __hadd2(*(__half2*)&hacc[mt][nt][1], *(__half2*)&hacc[mt][nt][3]);
                    float2 f0 = __half22float2(h0);
                    float2 f1 = __half22float2(h1);
                    v00 = fmaxf(f0.x + b0, 0.f);
                    v01 = fmaxf(f0.y + b1, 0.f);
                    v10 = fmaxf(f1.x + b0, 0.f);
                    v11 = fmaxf(f1.y + b1, 0.f);
                } else {
                    v00 = fmaxf(acc[mt][nt][0] + b0, 0.f);
                    v01 = fmaxf(acc[mt][nt][1] + b1, 0.f);
                    v10 = fmaxf(acc[mt][nt][2] + b0, 0.f);
                    v11 = fmaxf(acc[mt][nt][3] + b1, 0.f);
                }
                if (LASTL) {
                    float* C = (float*)Cout;
                    *(float2*)&C[m0 * CSTR + c0] = make_float2(v00, v01);
                    *(float2*)&C[m1 * CSTR + c0] = make_float2(v10, v11);
                } else {
                    __half* C = (__half*)Cout;
                    int s = slot32(c0);       // even c0 -> half2 aligned
                    *(__half2*)&C[m0 * CSTR + s] = __floats2half2_rn(v00, v01);
                    *(__half2*)&C[m1 * CSTR + s] = __floats2half2_rn(v10, v11);
                }
            }
        }
    }
}

// ---------------- kernel 3 (ncu launch index 3): fused MLP ----------------
// smem bytes: bufB_h 64*544*2=69632 (overlay bufF f32 64*132*4=33792)
//             bufA_h 64*288*2=36864 (overlay sSum 2*13*128*4=13312 after L4)
//             bufI_h 64*32*2=4096,  extras 768   -> total 111360 (2 CTAs/SM)
#define SMEM_BYTES (69632 + 36864 + 4096 + 768)

__global__ __launch_bounds__(NTHR, 2)
void mlp_kernel(const float* __restrict__ pos, const float* __restrict__ x,
                const int* __restrict__ y,
                const float* __restrict__ be1, const float* __restrict__ be2,
                const float* __restrict__ b1,  const float* __restrict__ b2,
                float* __restrict__ out, int P, int Npts)
{
    extern __shared__ __align__(16) char smraw[];
    __half* bufB = (__half*)smraw;                      // [64][544]
    __half* bufA = (__half*)(smraw + 69632);            // [64][288]
    __half* bufI = (__half*)(smraw + 69632 + 36864);    // [64][32]
    float*  sInv = (float*)(smraw + 69632 + 36864 + 4096);   // 64
    float*  sLbl = sInv + 64;                           // 64
    int*    sLab = (int*)(sLbl + 64);                   // 64
    float*  bufF = (float*)smraw;                       // overlay [64][132]
    float*  sSum = (float*)(smraw + 69632);             // overlay 2*13*128

    const int tid  = threadIdx.x;
    const int lane = tid & 31, warp = tid >> 5;
    const int base = blockIdx.x * BM;

    // ---- load inputs into bufI [64][32] (slot32 permuted, fp16, zero pad) ----
    for (int i = tid; i < BM * 32; i += NTHR) {
        int m = i >> 5, c = i & 31;
        int p = base + m;
        float v = 0.f;
        if (p < P && c < 7) {
            int b = p / Npts, n = p - b * Npts;
            if (c < 4) v = x[((size_t)b * 4 + c) * Npts + n];
            else       v = pos[(size_t)p * 3 + (c - 4)];
        }
        bufI[m * 32 + slot32(c)] = __float2half(v);
    }
    if (tid < BM) {
        int p = base + tid;
        int l = (p < P) ? y[p] : 0;
        sLab[tid] = l;
        float cnt = (float)g_counts[l];
        sLbl[tid] = (cnt >= MINPTS) ? (float)l : -1.f;
    }
    __syncthreads();

    // ---- MLP chain (fp16 tensor cores; L2/L3 f16 dual-chain accumulation) ----
    mma_layer<16,  256, 32,  288, 4, 4, false, false>(g_wp + OFF1, be1, bufI, bufA, warp, lane);
    __syncthreads();
    mma_layer<256, 512, 288, 544, 4, 4, false, true >(g_wp + OFF2, be2, bufA, bufB, warp, lane);
    __syncthreads();
    mma_layer<512, 256, 544, 288, 4, 4, false, true >(g_wp + OFF3, b1,  bufB, bufA, warp, lane);
    __syncthreads();
    mma_layer<256, 128, 288, 132, 4, 2, true,  false>(g_wp + OFF4, b2,  bufA, bufF, warp, lane);
    __syncthreads();

    // ---- zero sum overlay (bufA dead now) + L2 norms ----
    for (int i = tid; i < 2 * NCLS * PD; i += NTHR) sSum[i] = 0.f;
    if (tid < BM) {
        float s = 0.f;
        const float4* rr = (const float4*)(bufF + tid * 132);
        #pragma unroll
        for (int j = 0; j < 32; j++) {
            float4 qv = rr[j];
            s += qv.x * qv.x + qv.y * qv.y + qv.z * qv.z + qv.w * qv.w;
        }
        sInv[tid] = 1.f / fmaxf(sqrtf(s), 1e-12f);
    }
    __syncthreads();

    // ---- per-class sums (2 race-free shared copies) ----
    {
        int n = tid & 127, half = tid >> 7;
        float* dst = sSum + half * NCLS * PD + n;
        for (int mm = 0; mm < 32; mm++) {
            int m = (half << 5) + mm;
            if (base + m < P) {
                int l = sLab[m];
                dst[l * PD] += bufF[m * 132 + n] * sInv[m];
            }
        }
    }
    __syncthreads();
    for (int i = tid; i < NCLS * PD; i += NTHR)
        atomicAdd(&g_sums[i], sSum[i] + sSum[NCLS * PD + i]);

    // ---- write current_prior rows [64][129] ----
    size_t gbase = (size_t)base * 129;
    for (int i = tid; i < BM * 129; i += NTHR) {
        int m = i / 129, c = i - m * 129;
        if (base + m < P)
            out[gbase + i] = (c < PD) ? bufF[m * 132 + c] * sInv[m] : sLbl[m];
    }
}

// ---------------- kernel 4: EMA prior update (one warp per class) ----------------
__global__ void prior_kernel(const float* __restrict__ prior, float* __restrict__ out, int P) {
    int w = threadIdx.x >> 5;
    int lane = threadIdx.x & 31;
    if (w >= NCLS) return;
    float cnt = (float)g_counts[w];
    bool valid = (cnt >= MINPTS);
    float inv_cnt = 1.f / fmaxf(cnt, 1.f);
    float4 s4 = *(const float4*)&g_sums[w * PD + lane * 4];
    float4 p4 = *(const float4*)&prior[w * PD + lane * 4];
    float v[4];
    float pe[4] = {p4.x, p4.y, p4.z, p4.w};
    float mn[4] = {s4.x * inv_cnt, s4.y * inv_cnt, s4.z * inv_cnt, s4.w * inv_cnt};
    float ss = 0.f;
    #pragma unroll
    for (int i = 0; i < 4; i++) {
        float cur = valid ? mn[i] : pe[i];
        v[i] = 0.999f * pe[i] + 0.001f * cur;
        ss += v[i] * v[i];
    }
    #pragma unroll
    for (int o = 16; o > 0; o >>= 1) ss += __shfl_xor_sync(0xffffffffu, ss, o);
    float inv = 1.f / fmaxf(sqrtf(ss), 1e-12f);
    *(float4*)&out[(size_t)P * 129 + w * PD + lane * 4] =
        make_float4(v[0] * inv, v[1] * inv, v[2] * inv, v[3] * inv);
}

// ---------------- launch (mlp_kernel is launch index 3) ----------------
extern "C" void kernel_launch(void* const* d_in, const int* in_sizes, int n_in,
                              void* d_out, int out_size)
{
    const float* pos = (const float*)d_in[0];
    const float* x   = (const float*)d_in[1];
    const int*   y   = (const int*)  d_in[2];
    const float* We1 = (const float*)d_in[3];
    const float* be1 = (const float*)d_in[4];
    const float* We2 = (const float*)d_in[5];
    const float* be2 = (const float*)d_in[6];
    const float* W1  = (const float*)d_in[7];
    const float* b1  = (const float*)d_in[8];
    const float* W2  = (const float*)d_in[9];
    const float* b2  = (const float*)d_in[10];
    const float* pe  = (const float*)d_in[11];
    float* out = (float*)d_out;

    int P    = in_sizes[2];
    int B    = in_sizes[0] / 3 / 40000;
    int Npts = (B > 0) ? (in_sizes[0] / 3 / B) : 40000;

    cudaFuncSetAttribute(mlp_kernel, cudaFuncAttributeMaxDynamicSharedMemorySize, SMEM_BYTES);

    zero_kernel<<<7, 256>>>();                               // 0
    count_kernel<<<(P + 255) / 256, 256>>>(y, P);            // 1
    pack_all_kernel<<<(WPTOT + 255) / 256, 256>>>(We1, We2, W1, W2); // 2
    mlp_kernel<<<(P + BM - 1) / BM, NTHR, SMEM_BYTES>>>(pos, x, y, be1, be2,
                                                        b1, b2, out, P, Npts); // 3
    prior_kernel<<<1, 416>>>(pe, out, P);                    // 4
}

// round 11
// speedup vs baseline: 1.2850x; 1.2850x over previous
#include <cuda_runtime.h>
#include <cuda_fp16.h>
#include <cstdint>

#define NCLS   13
#define PD     128
#define BM     64
#define NTHR   256
#define MINPTS 256.0f

// packed fp16 weight offsets (K padded to mult of 16), element counts in halfs
#define OFF1 0                    // 16*256   = 4096
#define OFF2 4096                 // 256*512  = 131072
#define OFF3 (OFF2 + 131072)      // 512*256  = 131072
#define OFF4 (OFF3 + 131072)      // 256*128  = 32768
#define WPTOT (OFF4 + 32768)

__device__ __align__(16) __half g_wp[WPTOT];
__device__ float  g_sums[NCLS * PD];
__device__ int    g_counts[NCLS];

// ---- fp16 mma m16n8k16, f32 accumulate ----
__device__ __forceinline__ void mma_f16(float* c, uint32_t a0, uint32_t a1,
                                        uint32_t a2, uint32_t a3,
                                        uint32_t b0, uint32_t b1) {
    asm volatile(
        "mma.sync.aligned.m16n8k16.row.col.f32.f16.f16.f32 "
        "{%0,%1,%2,%3}, {%4,%5,%6,%7}, {%8,%9}, {%0,%1,%2,%3};\n"
        : "+f"(c[0]), "+f"(c[1]), "+f"(c[2]), "+f"(c[3])
        : "r"(a0), "r"(a1), "r"(a2), "r"(a3), "r"(b0), "r"(b1));
}
// ---- fp16 mma m16n8k16, f16 accumulate (2 regs per tile: halves reg pressure) ----
__device__ __forceinline__ void mma_h16(uint32_t* c, uint32_t a0, uint32_t a1,
                                        uint32_t a2, uint32_t a3,
                                        uint32_t b0, uint32_t b1) {
    asm volatile(
        "mma.sync.aligned.m16n8k16.row.col.f16.f16.f16.f16 "
        "{%0,%1}, {%2,%3,%4,%5}, {%6,%7}, {%0,%1};\n"
        : "+r"(c[0]), "+r"(c[1])
        : "r"(a0), "r"(a1), "r"(a2), "r"(a3), "r"(b0), "r"(b1));
}

// column permutation within a 16-col k-group so (c, c+1, c+8, c+9) are one LDS.64
__device__ __forceinline__ int slot16(int c) {
    return (c & ~15) | ((c & 6) << 1) | ((c >> 2) & 2) | (c & 1);
}

// ---------------- kernel 0: zero scratch ----------------
__global__ void zero_kernel() {
    int i = blockIdx.x * blockDim.x + threadIdx.x;
    if (i < NCLS * PD) g_sums[i] = 0.f;
    if (i < NCLS) g_counts[i] = 0;
}

// ---------------- kernel 1: per-class counts ----------------
__global__ void count_kernel(const int* __restrict__ y, int P) {
    __shared__ int sc[NCLS];
    if (threadIdx.x < NCLS) sc[threadIdx.x] = 0;
    __syncthreads();
    for (int i = blockIdx.x * blockDim.x + threadIdx.x; i < P;
         i += gridDim.x * blockDim.x)
        atomicAdd(&sc[y[i]], 1);
    __syncthreads();
    if (threadIdx.x < NCLS) atomicAdd(&g_counts[threadIdx.x], sc[threadIdx.x]);
}

// ---------------- kernel 2: pack ALL weights (pair-packed for LDG.128) ----------------
// 8 halfs per (jp,kc,lane): [j=2jp frag (4h)][j=2jp+1 frag (4h)]
// frag halfs: [k0,k0+1,k0+8,k0+9], k0 = kc*16 + 2r, n = j*8 + q  (r=lane&3, q=lane>>2)
__device__ __forceinline__ void pack_one(const float* __restrict__ src,
                                         __half* __restrict__ dst,
                                         int p, int K, int N, int Ksrc) {
    int t = p & 3;
    int h = (p >> 2) & 1;
    int lane = (p >> 3) & 31;
    int rest = p >> 8;
    int kc = rest % (K >> 4);
    int jp = rest / (K >> 4);
    int r = lane & 3, q = lane >> 2;
    int j = jp * 2 + h;
    int k = kc * 16 + 2 * r + (t & 1) + 8 * (t >> 1);
    int n = j * 8 + q;
    float v = (k < Ksrc) ? src[k * N + n] : 0.f;
    dst[p] = __float2half(v);
}
__global__ void pack_all_kernel(const float* __restrict__ We1, const float* __restrict__ We2,
                                const float* __restrict__ W1, const float* __restrict__ W2) {
    int p = blockIdx.x * blockDim.x + threadIdx.x;
    if (p < 4096)                    pack_one(We1, g_wp + OFF1, p, 16, 256, 7);
    else if (p < 4096 + 131072)      pack_one(We2, g_wp + OFF2, p - 4096, 256, 512, 256);
    else if (p < 4096 + 262144)      pack_one(W1,  g_wp + OFF3, p - 135168, 512, 256, 512);
    else if (p < WPTOT)              pack_one(W2,  g_wp + OFF4, p - 266240, 256, 128, 256);
}

// ---------------- fp16 mma layer ----------------
// A in shared: row-major halfs [BM][ASTR], slot16-permuted k-groups.
// ASTR*2 mod 128 == 32 -> conflict-free LDS.64.
// W pair-packed: one uint4 per (jp,kc,lane) = fragments for j=2jp, 2jp+1.
// HACC: SINGLE-chain f16 accumulation (2 u32 regs per tile vs 4 f32) — frees
//       ~32 regs on the big layers so ptxas can pipeline B loads deeper.
template <int K, int N, int ASTR, int CSTR, int MT, int NT, bool LASTL, bool HACC>
__device__ __forceinline__ void mma_layer(
    const __half* __restrict__ Wp, const float* __restrict__ bias,
    const __half* __restrict__ Ash, void* __restrict__ Cout,
    int warp, int lane)
{
    const int r = lane & 3, q = lane >> 2;
    constexpr int SLICE = N / 8;
    constexpr int NCH = SLICE / (NT * 8);
    constexpr int KC = K / 16;
    #pragma unroll
    for (int ch = 0; ch < NCH; ch++) {
        const int nbase = warp * SLICE + ch * NT * 8;
        const int jp0 = nbase >> 4;
        float acc[HACC ? 1 : MT][NT][HACC ? 1 : 4];
        uint32_t hacc[HACC ? MT : 1][NT][HACC ? 2 : 1];
        if (HACC) {
            #pragma unroll
            for (int mt = 0; mt < MT; mt++)
                #pragma unroll
                for (int nt = 0; nt < NT; nt++) {
                    hacc[mt][nt][0] = 0u;
                    hacc[mt][nt][1] = 0u;
                }
        } else {
            #pragma unroll
            for (int mt = 0; mt < MT; mt++)
                #pragma unroll
                for (int nt = 0; nt < NT; nt++)
                    #pragma unroll
                    for (int i = 0; i < 4; i++) acc[mt][nt][i] = 0.f;
        }

        #pragma unroll 8
        for (int kc = 0; kc < KC; kc++) {
            uint2 a[MT][2];
            #pragma unroll
            for (int mt = 0; mt < MT; mt++) {
                a[mt][0] = *(const uint2*)&Ash[(mt * 16 + q)     * ASTR + kc * 16 + r * 4];
                a[mt][1] = *(const uint2*)&Ash[(mt * 16 + q + 8) * ASTR + kc * 16 + r * 4];
            }
            uint4 bp[NT / 2];
            #pragma unroll
            for (int n2 = 0; n2 < NT / 2; n2++)
                bp[n2] = *(const uint4*)&Wp[(size_t)(((jp0 + n2) * KC + kc) * 32 + lane) * 8];
            if (HACC) {
                #pragma unroll
                for (int mt = 0; mt < MT; mt++)
                    #pragma unroll
                    for (int n2 = 0; n2 < NT / 2; n2++) {
                        mma_h16(hacc[mt][2*n2],   a[mt][0].x, a[mt][1].x,
                                a[mt][0].y, a[mt][1].y, bp[n2].x, bp[n2].y);
                        mma_h16(hacc[mt][2*n2+1], a[mt][0].x, a[mt][1].x,
                                a[mt][0].y, a[mt][1].y, bp[n2].z, bp[n2].w);
                    }
            } else {
                #pragma unroll
                for (int mt = 0; mt < MT; mt++)
                    #pragma unroll
                    for (int n2 = 0; n2 < NT / 2; n2++) {
                        mma_f16(acc[mt][2*n2],   a[mt][0].x, a[mt][1].x,
                                a[mt][0].y, a[mt][1].y, bp[n2].x, bp[n2].y);
                        mma_f16(acc[mt][2*n2+1], a[mt][0].x, a[mt][1].x,
                                a[mt][0].y, a[mt][1].y, bp[n2].z, bp[n2].w);
                    }
            }
        }
        // epilogue: bias + relu
        #pragma unroll
        for (int nt = 0; nt < NT; nt++) {
            int c0 = nbase + nt * 8 + 2 * r;
            float b0 = bias[c0], b1 = bias[c0 + 1];
            #pragma unroll
            for (int mt = 0; mt < MT; mt++) {
                int m0 = mt * 16 + q, m1 = m0 + 8;
                float v00, v01, v10, v11;
                if (HACC) {
                    float2 f0 = __half22float2(*(__half2*)&hacc[mt][nt][0]);
                    float2 f1 = __half22float2(*(__half2*)&hacc[mt][nt][1]);
                    v00 = fmaxf(f0.x + b0, 0.f);
                    v01 = fmaxf(f0.y + b1, 0.f);
                    v10 = fmaxf(f1.x + b0, 0.f);
                    v11 = fmaxf(f1.y + b1, 0.f);
                } else {
                    v00 = fmaxf(acc[mt][nt][0] + b0, 0.f);
                    v01 = fmaxf(acc[mt][nt][1] + b1, 0.f);
                    v10 = fmaxf(acc[mt][nt][2] + b0, 0.f);
                    v11 = fmaxf(acc[mt][nt][3] + b1, 0.f);
                }
                if (LASTL) {
                    float* C = (float*)Cout;
                    *(float2*)&C[m0 * CSTR + c0] = make_float2(v00, v01);
                    *(float2*)&C[m1 * CSTR + c0] = make_float2(v10, v11);
                } else {
                    __half* C = (__half*)Cout;
                    int s = slot16(c0);
                    *(__half2*)&C[m0 * CSTR + s] = __floats2half2_rn(v00, v01);
                    *(__half2*)&C[m1 * CSTR + s] = __floats2half2_rn(v10, v11);
                }
            }
        }
    }
}

// ---------------- kernel 3 (ncu launch index 3): fused MLP ----------------
// smem bytes: bufB_h 64*528*2=67584 (overlay bufF f32 64*132*4=33792)
//             bufA_h 64*272*2=34816 (overlay sSum 2*13*128*4=13312 after L4)
//             bufI_h 64*16*2=2048,  extras 768
#define SMEM_BYTES (67584 + 34816 + 2048 + 768)

__global__ __launch_bounds__(NTHR, 2)
void mlp_kernel(const float* __restrict__ pos, const float* __restrict__ x,
                const int* __restrict__ y,
                const float* __restrict__ be1, const float* __restrict__ be2,
                const float* __restrict__ b1,  const float* __restrict__ b2,
                float* __restrict__ out, int P, int Npts)
{
    extern __shared__ __align__(16) char smraw[];
    __half* bufB = (__half*)smraw;                      // [64][528]
    __half* bufA = (__half*)(smraw + 67584);            // [64][272]
    __half* bufI = (__half*)(smraw + 67584 + 34816);    // [64][16]
    float*  sInv = (float*)(smraw + 67584 + 34816 + 2048);   // 64
    float*  sLbl = sInv + 64;                           // 64
    int*    sLab = (int*)(sLbl + 64);                   // 64
    float*  bufF = (float*)smraw;                       // overlay [64][132]
    float*  sSum = (float*)(smraw + 67584);             // overlay 2*13*128

    const int tid  = threadIdx.x;
    const int lane = tid & 31, warp = tid >> 5;
    const int base = blockIdx.x * BM;

    // ---- load inputs into bufI [64][16] (permuted slots, fp16) ----
    for (int i = tid; i < BM * 16; i += NTHR) {
        int m = i >> 4, c = i & 15;
        int p = base + m;
        float v = 0.f;
        if (p < P && c < 7) {
            int b = p / Npts, n = p - b * Npts;
            if (c < 4) v = x[((size_t)b * 4 + c) * Npts + n];
            else       v = pos[(size_t)p * 3 + (c - 4)];
        }
        bufI[m * 16 + slot16(c)] = __float2half(v);
    }
    if (tid < BM) {
        int p = base + tid;
        int l = (p < P) ? y[p] : 0;
        sLab[tid] = l;
        float cnt = (float)g_counts[l];
        sLbl[tid] = (cnt >= MINPTS) ? (float)l : -1.f;
    }
    __syncthreads();

    // ---- MLP chain (fp16 tensor cores; L2/L3 single-chain f16 accumulation) ----
    mma_layer<16,  256, 16,  272, 4, 4, false, false>(g_wp + OFF1, be1, bufI, bufA, warp, lane);
    __syncthreads();
    mma_layer<256, 512, 272, 528, 4, 4, false, true >(g_wp + OFF2, be2, bufA, bufB, warp, lane);
    __syncthreads();
    mma_layer<512, 256, 528, 272, 4, 4, false, true >(g_wp + OFF3, b1,  bufB, bufA, warp, lane);
    __syncthreads();
    mma_layer<256, 128, 272, 132, 4, 2, true,  false>(g_wp + OFF4, b2,  bufA, bufF, warp, lane);
    __syncthreads();

    // ---- zero sum overlay (bufA dead now) + L2 norms ----
    for (int i = tid; i < 2 * NCLS * PD; i += NTHR) sSum[i] = 0.f;
    if (tid < BM) {
        float s = 0.f;
        const float4* rr = (const float4*)(bufF + tid * 132);
        #pragma unroll
        for (int j = 0; j < 32; j++) {
            float4 qv = rr[j];
            s += qv.x * qv.x + qv.y * qv.y + qv.z * qv.z + qv.w * qv.w;
        }
        sInv[tid] = 1.f / fmaxf(sqrtf(s), 1e-12f);
    }
    __syncthreads();

    // ---- per-class sums (2 race-free shared copies) ----
    {
        int n = tid & 127, half = tid >> 7;
        float* dst = sSum + half * NCLS * PD + n;
        for (int mm = 0; mm < 32; mm++) {
            int m = (half << 5) + mm;
            if (base + m < P) {
                int l = sLab[m];
                dst[l * PD] += bufF[m * 132 + n] * sInv[m];
            }
        }
    }
    __syncthreads();
    for (int i = tid; i < NCLS * PD; i += NTHR)
        atomicAdd(&g_sums[i], sSum[i] + sSum[NCLS * PD + i]);

    // ---- write current_prior rows [64][129] ----
    size_t gbase = (size_t)base * 129;
    for (int i = tid; i < BM * 129; i += NTHR) {
        int m = i / 129, c = i - m * 129;
        if (base + m < P)
            out[gbase + i] = (c < PD) ? bufF[m * 132 + c] * sInv[m] : sLbl[m];
    }
}

// ---------------- kernel 4: EMA prior update (one warp per class) ----------------
__global__ void prior_kernel(const float* __restrict__ prior, float* __restrict__ out, int P) {
    int w = threadIdx.x >> 5;
    int lane = threadIdx.x & 31;
    if (w >= NCLS) return;
    float cnt = (float)g_counts[w];
    bool valid = (cnt >= MINPTS);
    float inv_cnt = 1.f / fmaxf(cnt, 1.f);
    float4 s4 = *(const float4*)&g_sums[w * PD + lane * 4];
    float4 p4 = *(const float4*)&prior[w * PD + lane * 4];
    float v[4];
    float pe[4] = {p4.x, p4.y, p4.z, p4.w};
    float mn[4] = {s4.x * inv_cnt, s4.y * inv_cnt, s4.z * inv_cnt, s4.w * inv_cnt};
    float ss = 0.f;
    #pragma unroll
    for (int i = 0; i < 4; i++) {
        float cur = valid ? mn[i] : pe[i];
        v[i] = 0.999f * pe[i] + 0.001f * cur;
        ss += v[i] * v[i];
    }
    #pragma unroll
    for (int o = 16; o > 0; o >>= 1) ss += __shfl_xor_sync(0xffffffffu, ss, o);
    float inv = 1.f / fmaxf(sqrtf(ss), 1e-12f);
    *(float4*)&out[(size_t)P * 129 + w * PD + lane * 4] =
        make_float4(v[0] * inv, v[1] * inv, v[2] * inv, v[3] * inv);
}

// ---------------- launch (mlp_kernel is launch index 3) ----------------
extern "C" void kernel_launch(void* const* d_in, const int* in_sizes, int n_in,
                              void* d_out, int out_size)
{
    const float* pos = (const float*)d_in[0];
    const float* x   = (const float*)d_in[1];
    const int*   y   = (const int*)  d_in[2];
    const float* We1 = (const float*)d_in[3];
    const float* be1 = (const float*)d_in[4];
    const float* We2 = (const float*)d_in[5];
    const float* be2 = (const float*)d_in[6];
    const float* W1  = (const float*)d_in[7];
    const float* b1  = (const float*)d_in[8];
    const float* W2  = (const float*)d_in[9];
    const float* b2  = (const float*)d_in[10];
    const float* pe  = (const float*)d_in[11];
    float* out = (float*)d_out;

    int P    = in_sizes[2];
    int B    = in_sizes[0] / 3 / 40000;
    int Npts = (B > 0) ? (in_sizes[0] / 3 / B) : 40000;

    cudaFuncSetAttribute(mlp_kernel, cudaFuncAttributeMaxDynamicSharedMemorySize, SMEM_BYTES);

    zero_kernel<<<7, 256>>>();                               // 0
    count_kernel<<<(P + 255) / 256, 256>>>(y, P);            // 1
    pack_all_kernel<<<(WPTOT + 255) / 256, 256>>>(We1, We2, W1, W2); // 2
    mlp_kernel<<<(P + BM - 1) / BM, NTHR, SMEM_BYTES>>>(pos, x, y, be1, be2,
                                                        b1, b2, out, P, Npts); // 3
    prior_kernel<<<1, 416>>>(pe, out, P);                    // 4
}